// round 10
// baseline (speedup 1.0000x reference)
#include <cuda_runtime.h>
#include <cstdint>

#define TT 1000
#define BB 512
#define IDM 32
#define HH 64
#define NHIST 5
#define CLN 8
#define FULLM 0xffffffffu

// Kalman gains per step: layout [t][o*64 + i]
__device__ __align__(16) float g_U[TT * 192];
// per-step "correction active" flag (0 => K_t == 0, skip correction)
__device__ int g_act[TT];
// CW = C @ W_mlp  (3 x 320), Cb = C @ b_mlp (3)
__device__ __align__(16) float g_CW[3 * 320];
__device__ __align__(16) float g_Cb[4];
// cluster-shared Riccati state (L2-resident)
__device__ __align__(16) float g_cov[4096];
__device__ __align__(16) float g_P[4096];
__device__ __align__(16) float g_Ucur[192];
__device__ __align__(16) float g_CP[192];
__device__ int g_done;

// ---- packed f32x2 helpers (Blackwell FFMA2 path, PTX-only) ----
__device__ __forceinline__ void fma2(unsigned long long& d,
                                     unsigned long long a,
                                     unsigned long long b) {
    asm("fma.rn.f32x2 %0, %1, %2, %0;" : "+l"(d) : "l"(a), "l"(b));
}
__device__ __forceinline__ unsigned long long pack2(float lo, float hi) {
    unsigned long long r;
    asm("mov.b64 %0, {%1, %2};" : "=l"(r) : "f"(lo), "f"(hi));
    return r;
}
__device__ __forceinline__ float2 unpack2(unsigned long long v) {
    float2 r;
    asm("mov.b64 {%0, %1}, %2;" : "=f"(r.x), "=f"(r.y) : "l"(v));
    return r;
}

#define CLUSTER_SYNC() do { \
    asm volatile("barrier.cluster.arrive.aligned;" ::: "memory"); \
    asm volatile("barrier.cluster.wait.aligned;" ::: "memory"); \
} while (0)

// ======================================================================
// Producer: prep (CW fold) + Riccati chain -> K_t.
// 8-CTA cluster; each iteration's GEMMs split 8 rows/block.
// Exit when max|K| <= 1e-6 (K -> 0 geometrically); zero-fill tail.
// ======================================================================
__global__ void __cluster_dims__(CLN, 1, 1) __launch_bounds__(256, 1)
cov_kernel(const float* __restrict__ W_hh, const float* __restrict__ Cmat,
           const float* __restrict__ W_mlp, const float* __restrict__ b_mlp) {
    __shared__ __align__(16) float sAt[4096];  // At[k][j] = W_hh[j*64+k]
    __shared__ __align__(16) float sE[8][64];
    __shared__ float sC[192];
    __shared__ float sY[192];
    __shared__ float sS[9];
    __shared__ float sSi[9];
    __shared__ float sUp[192];
    __shared__ int sctl[2];

    const int tid  = threadIdx.x;
    const int rank = blockIdx.x;          // == cluster rank (grid = 1 cluster)
    const int ry   = tid >> 5;
    const int lane = tid & 31;
    const int j0   = lane * 2;
    const int r    = rank * 8 + ry;       // global row owned by this thread

    // ---- init ----
    for (int idx = tid; idx < 4096; idx += 256) {
        int k = idx >> 6, j = idx & 63;
        sAt[idx] = W_hh[j * 64 + k];
    }
    for (int idx = tid; idx < 192; idx += 256) sC[idx] = Cmat[idx];
    for (int idx = tid; idx < 512; idx += 256) {
        int rr = rank * 8 + (idx >> 6), j = idx & 63;
        __stcg(&g_cov[rr * 64 + j], (rr == j) ? 1.f : 0.f);
    }
    // CW fold split across blocks (960 / 8 = 120 per block)
    for (int q = tid; q < 120; q += 256) {
        int idx = rank * 120 + q;
        int o = idx / 320, m = idx - o * 320;
        float acc = 0.f;
        #pragma unroll 8
        for (int j = 0; j < 64; j++) acc += Cmat[o * 64 + j] * W_mlp[j * 320 + m];
        g_CW[idx] = acc;
    }
    if (rank == 0) {
        if (tid < 3) {
            float acc = 0.f;
            for (int j = 0; j < 64; j++) acc += Cmat[tid * 64 + j] * b_mlp[j];
            g_Cb[tid] = acc;
        }
        if (tid >= 8 && tid < 8 + NHIST) g_act[tid - 8] = 0;
        if (tid == 100) __stcg(&g_done, 0);
        if (tid < 192) sUp[tid] = 0.f;
    }
    __syncthreads();
    __threadfence();
    CLUSTER_SYNC();

    for (int t = NHIST; t < TT; t++) {
        // ---- Phase A: E rows (smem), then P rows -> global ----
        {
            unsigned long long acc = 0;
            #pragma unroll 8
            for (int k = 0; k < 64; k++) {
                unsigned long long cv =
                    __ldcg((const unsigned long long*)&g_cov[k * 64 + j0]);
                float av = sAt[k * 64 + r];          // A[r][k] (broadcast)
                fma2(acc, pack2(av, av), cv);
            }
            float2 ev = unpack2(acc);
            sE[ry][j0] = ev.x; sE[ry][j0 + 1] = ev.y;
        }
        __syncthreads();
        {
            unsigned long long acc = 0;
            #pragma unroll 8
            for (int k = 0; k < 64; k++) {
                float ek = sE[ry][k];                // broadcast
                unsigned long long atv =
                    *(const unsigned long long*)&sAt[k * 64 + j0]; // A[j][k]
                fma2(acc, pack2(ek, ek), atv);
            }
            __stcg((float2*)&g_P[r * 64 + j0], unpack2(acc));
        }
        __threadfence();
        CLUSTER_SYNC();

        // ---- Phase B (block 0): Y, S, Si, U=K, CP, exit decision ----
        if (rank == 0) {
            if (tid < 2) sctl[tid] = 0;
            __syncthreads();
            if (tid < 192) {                         // Y = P @ C^T
                int o = tid >> 6, i = tid & 63;
                float acc = 0.f;
                #pragma unroll 8
                for (int k = 0; k < 64; k++)
                    acc += __ldcg(&g_P[i * 64 + k]) * sC[o * 64 + k];
                sY[i * 3 + o] = acc;
            }
            __syncthreads();
            if (tid < 9) {                           // S = C @ Y + I
                int o1 = tid / 3, o2 = tid - o1 * 3;
                float acc = (o1 == o2) ? 1.f : 0.f;
                for (int k = 0; k < 64; k++)
                    acc += sC[o1 * 64 + k] * sY[k * 3 + o2];
                sS[tid] = acc;
            }
            __syncthreads();
            if (tid == 0) {                          // Si = inv(S)
                float a = sS[0], b = sS[1], c = sS[2];
                float d = sS[3], e = sS[4], f = sS[5];
                float g = sS[6], h = sS[7], i2 = sS[8];
                float A0 =  (e * i2 - f * h);
                float A1 = -(d * i2 - f * g);
                float A2 =  (d * h  - e * g);
                float B0 = -(b * i2 - c * h);
                float B1 =  (a * i2 - c * g);
                float B2 = -(a * h  - b * g);
                float C0 =  (b * f - c * e);
                float C1 = -(a * f - c * d);
                float C2 =  (a * e - b * d);
                float det = a * A0 + b * A1 + c * A2;
                float id = 1.f / det;
                sSi[0] = A0 * id; sSi[1] = B0 * id; sSi[2] = C0 * id;
                sSi[3] = A1 * id; sSi[4] = B1 * id; sSi[5] = C1 * id;
                sSi[6] = A2 * id; sSi[7] = B2 * id; sSi[8] = C2 * id;
            }
            __syncthreads();
            if (tid < 192) {                         // U = Y @ Si, CP = C @ P
                int o = tid >> 6, i = tid & 63;
                float u = sY[i * 3 + 0] * sSi[0 + o]
                        + sY[i * 3 + 1] * sSi[3 + o]
                        + sY[i * 3 + 2] * sSi[6 + o];
                __stcg(&g_U[(size_t)t * 192 + tid], u);
                __stcg(&g_Ucur[tid], u);
                float dd = fabsf(u - sUp[tid]);
                sUp[tid] = u;
                atomicMax(&sctl[0], __float_as_int(dd));
                atomicMax(&sctl[1], __float_as_int(fabsf(u)));
                float cp = 0.f;
                #pragma unroll 8
                for (int k = 0; k < 64; k++)
                    cp += sC[o * 64 + k] * __ldcg(&g_P[k * 64 + i]);
                __stcg(&g_CP[tid], cp);
            }
            __syncthreads();
            if (tid == 0) {
                float md = __int_as_float(sctl[0]);
                float ma = __int_as_float(sctl[1]);
                int dn = 0;
                if (ma <= 1e-6f)           dn = 2;   // K negligible
                else if (md <= 1e-6f * ma) dn = 1;   // K stationary
                __stcg(&g_done, dn);
                g_act[t] = 1;
            }
            __threadfence();
        }
        CLUSTER_SYNC();

        // ---- Phase C (all blocks): cov rows update, exit handling ----
        int dn = __ldcg(&g_done);
        {
            float2 pv  = __ldcg((const float2*)&g_P[r * 64 + j0]);
            float  u0  = __ldcg(&g_Ucur[r]);
            float  u1  = __ldcg(&g_Ucur[64 + r]);
            float  u2  = __ldcg(&g_Ucur[128 + r]);
            float2 cp0 = __ldcg((const float2*)&g_CP[j0]);
            float2 cp1 = __ldcg((const float2*)&g_CP[64 + j0]);
            float2 cp2 = __ldcg((const float2*)&g_CP[128 + j0]);
            float nc0 = pv.x - (u0 * cp0.x + u1 * cp1.x + u2 * cp2.x);
            float nc1 = pv.y - (u0 * cp0.y + u1 * cp1.y + u2 * cp2.y);
            __stcg((float2*)&g_cov[r * 64 + j0], make_float2(nc0, nc1));
        }
        if (dn) {       // uniform across cluster: fill tail, exit
            const int dz = (dn == 2);
            float uv = 0.f;
            if (tid < 192) uv = dz ? 0.f : __ldcg(&g_Ucur[tid]);
            for (int tt = t + 1 + rank; tt < TT; tt += CLN) {
                if (tid < 192) __stcg(&g_U[(size_t)tt * 192 + tid], uv);
                if (tid == 200) g_act[tt] = dz ? 0 : 1;
            }
            break;
        }
        __threadfence();
        CLUSTER_SYNC();
    }
}

// ======================================================================
// Consumer: block = 64 threads = 1 batch row; lane owns output dim
// j = tid. Weights register-stationary (persistent-RNN); per-step smem
// traffic is broadcast-only (h + x). One __syncthreads per step.
// ======================================================================
__global__ void __launch_bounds__(64, 1)
seq_kernel(const float* __restrict__ x,
           const float* __restrict__ W_ih, const float* __restrict__ b_ih,
           const float* __restrict__ W_hh, const float* __restrict__ b_hh,
           const float* __restrict__ C,
           float* __restrict__ out, float* __restrict__ hlast) {
    __shared__ __align__(16) float sh[2][64];   // parity-buffered hidden
    __shared__ __align__(16) float sx[2][32];   // parity-buffered x
    __shared__ float sred[2][4];                // correction warp partials

    const int tid  = threadIdx.x;
    const int w    = tid >> 5;
    const int lane = tid & 31;
    const int j    = tid;          // output dim owned by this lane
    const int row  = blockIdx.x;

    // ---- weights into registers (f32x2-packed) ----
    unsigned long long whh[32], wih[16];
    #pragma unroll
    for (int p = 0; p < 32; p++)
        whh[p] = *(const unsigned long long*)&W_hh[j * HH + 2 * p];
    #pragma unroll
    for (int p = 0; p < 16; p++)
        wih[p] = *(const unsigned long long*)&W_ih[j * IDM + 2 * p];

    const float Cj0 = C[j], Cj1 = C[64 + j], Cj2 = C[128 + j];
    const float bj  = b_ih[j] + b_hh[j];
    const float cb0 = g_Cb[0], cb1 = g_Cb[1], cb2 = g_Cb[2];

    // ---- init state ----
    sh[0][j] = 0.f;
    float hcur = 0.f;
    float hist[NHIST] = {0.f, 0.f, 0.f, 0.f, 0.f};
    float xn1 = 0.f, xn2 = 0.f;
    if (w == 0) {
        sx[0][lane] = x[(size_t)row * IDM + lane];
        xn1 = x[((size_t)1 * BB + row) * IDM + lane];
        xn2 = x[((size_t)2 * BB + row) * IDM + lane];
    }
    int actc = 0, actn = 0;     // g_act[0], g_act[1] known 0
    float k0 = 0.f, k1 = 0.f, k2 = 0.f;
    int par = 0;
    __syncthreads();

    for (int t = 0; t < TT; t++) {
        // ---- prefetch x[t+3], act[t+2], K[t+1] ----
        float xn3 = 0.f;
        if (w == 0 && t + 3 < TT)
            xn3 = x[((size_t)(t + 3) * BB + row) * IDM + lane];
        int actn2 = (t + 2 < TT) ? g_act[t + 2] : 0;
        float kn0 = 0.f, kn1 = 0.f, kn2 = 0.f;
        if (actn) {
            const float* Ut = &g_U[(size_t)(t + 1) * 192];
            kn0 = Ut[j]; kn1 = Ut[64 + j]; kn2 = Ut[128 + j];
        }

        // ---- GEMV: broadcast reads, register weights, FFMA2 ----
        unsigned long long a0 = 0, a1 = 0, a2 = 0, a3 = 0;
        const ulonglong2* hp = (const ulonglong2*)sh[par];
        #pragma unroll
        for (int q = 0; q < 16; q++) {
            ulonglong2 hv = hp[q];               // h[4q..4q+3]
            if (q & 1) { fma2(a2, hv.x, whh[2 * q]); fma2(a3, hv.y, whh[2 * q + 1]); }
            else       { fma2(a0, hv.x, whh[2 * q]); fma2(a1, hv.y, whh[2 * q + 1]); }
        }
        const ulonglong2* xp = (const ulonglong2*)sx[par];
        #pragma unroll
        for (int q = 0; q < 8; q++) {
            ulonglong2 xv = xp[q];               // x[4q..4q+3]
            if (q & 1) { fma2(a2, xv.x, wih[2 * q]); fma2(a3, xv.y, wih[2 * q + 1]); }
            else       { fma2(a0, xv.x, wih[2 * q]); fma2(a1, xv.y, wih[2 * q + 1]); }
        }
        float2 A0 = unpack2(a0), A1 = unpack2(a1), A2 = unpack2(a2), A3 = unpack2(a3);
        float pre = bj + (((A0.x + A0.y) + (A1.x + A1.y))
                        + ((A2.x + A2.y) + (A3.x + A3.y)));
        float ho = hcur * 0.8f + fmaxf(pre, 0.f) * 0.2f;

        // ---- Kalman correction (rarely active) ----
        if (actc) {
            float p0 = -Cj0 * ho, p1 = -Cj1 * ho, p2 = -Cj2 * ho;
            #pragma unroll
            for (int sd = 0; sd < NHIST; sd++) {
                float hv = hist[sd];
                p0 += g_CW[0 * 320 + sd * 64 + j] * hv;
                p1 += g_CW[1 * 320 + sd * 64 + j] * hv;
                p2 += g_CW[2 * 320 + sd * 64 + j] * hv;
            }
            #pragma unroll
            for (int off = 16; off; off >>= 1) {
                p0 += __shfl_xor_sync(FULLM, p0, off);
                p1 += __shfl_xor_sync(FULLM, p1, off);
                p2 += __shfl_xor_sync(FULLM, p2, off);
            }
            if (lane == 0) {
                sred[w][0] = p0; sred[w][1] = p1; sred[w][2] = p2;
            }
            __syncthreads();
            p0 = sred[0][0] + sred[1][0] + cb0;
            p1 = sred[0][1] + sred[1][1] + cb1;
            p2 = sred[0][2] + sred[1][2] + cb2;
            ho += k0 * p0 + k1 * p1 + k2 * p2;
        }

        // ---- history shift (registers) ----
        #pragma unroll
        for (int sd = 0; sd < NHIST - 1; sd++) hist[sd] = hist[sd + 1];
        hist[NHIST - 1] = ho;

        // ---- publish state, write output, advance pipeline ----
        sh[par ^ 1][j] = ho;
        if (w == 0) sx[par ^ 1][lane] = xn1;
        out[((size_t)t * BB + row) * HH + j] = ho;
        __syncthreads();

        hcur = ho;
        xn1 = xn2; xn2 = xn3;
        actc = actn; actn = actn2;
        k0 = kn0; k1 = kn1; k2 = kn2;
        par ^= 1;
    }

    if (hlast) hlast[(size_t)row * HH + j] = hcur;
}

// ======================================================================
extern "C" void kernel_launch(void* const* d_in, const int* in_sizes, int n_in,
                              void* d_out, int out_size) {
    const float* x     = (const float*)d_in[0];
    const float* W_ih  = (const float*)d_in[1];
    const float* b_ih  = (const float*)d_in[2];
    const float* W_hh  = (const float*)d_in[3];
    const float* b_hh  = (const float*)d_in[4];
    const float* C     = (const float*)d_in[5];
    const float* W_mlp = (const float*)d_in[6];
    const float* b_mlp = (const float*)d_in[7];
    float* out = (float*)d_out;

    const long long main_elems = (long long)TT * BB * HH;
    float* hlast = ((long long)out_size >= main_elems + (long long)BB * HH)
                       ? out + main_elems : nullptr;

    cov_kernel<<<CLN, 256>>>(W_hh, C, W_mlp, b_mlp);
    seq_kernel<<<BB, 64>>>(x, W_ih, b_ih, W_hh, b_hh, C, out, hlast);
}

// round 11
// speedup vs baseline: 1.2396x; 1.2396x over previous
#include <cuda_runtime.h>
#include <cstdint>

#define TT 1000
#define BB 512
#define IDM 32
#define HH 64
#define NHIST 5
#define FULLM 0xffffffffu

// Kalman gains per step: layout [t][o*64 + i]
__device__ __align__(16) float g_U[TT * 192];
// first step with zero Kalman gain: correction active iff NHIST <= t < g_tcut
__device__ int g_tcut;
// CW = C @ W_mlp  (3 x 320), Cb = C @ b_mlp (3)
__device__ __align__(16) float g_CW[3 * 320];
__device__ __align__(16) float g_Cb[4];

// ---- packed f32x2 helpers (Blackwell FFMA2 path, PTX-only) ----
__device__ __forceinline__ void fma2(unsigned long long& d,
                                     unsigned long long a,
                                     unsigned long long b) {
    asm("fma.rn.f32x2 %0, %1, %2, %0;" : "+l"(d) : "l"(a), "l"(b));
}
__device__ __forceinline__ unsigned long long pack2(float lo, float hi) {
    unsigned long long r;
    asm("mov.b64 %0, {%1, %2};" : "=l"(r) : "f"(lo), "f"(hi));
    return r;
}
__device__ __forceinline__ float2 unpack2(unsigned long long v) {
    float2 r;
    asm("mov.b64 {%0, %1}, %2;" : "=f"(r.x), "=f"(r.y) : "l"(v));
    return r;
}

// ======================================================================
// Producer: prep (CW fold) + Riccati chain -> K_t. Single block,
// 512 threads (4 warps/SMSP for latency hiding), f32x2 GEMMs.
// Exit when max|K| <= 1e-6 (K -> 0 geometrically); seq skips the tail
// via g_tcut. Fallback: full chain (g_tcut = TT).
// ======================================================================
#define PD 66   // even => 8B-aligned float2 rows; padded => clean banks

struct PSmem {
    float A[64 * PD];     // A[i][k]
    float At[64 * PD];    // At[k][j] = A[j][k]
    float cov[64 * PD];
    float E[64 * PD];
    float P[64 * PD];
    float Cs[192];
    float Y[192];         // [i*3 + o]
    float S[9];
    float Si[9];
    float U[192];
    float Up[192];
    float CP[192];
    int ctl[2];
    int done;      // 0 = continue, 1 = tail<-U (stationary), 2 = K vanished
};

__global__ void __launch_bounds__(512, 1)
cov_kernel(const float* __restrict__ W_hh, const float* __restrict__ Cmat,
           const float* __restrict__ W_mlp, const float* __restrict__ b_mlp) {
    extern __shared__ char praw[];
    PSmem& s = *reinterpret_cast<PSmem*>(praw);
    const int tid = threadIdx.x;

    // ---- prep: CW = C @ W_mlp, Cb = C @ b_mlp ----
    for (int idx = tid; idx < 960; idx += 512) {
        int o = idx / 320, m = idx - o * 320;
        float acc = 0.f;
        #pragma unroll 8
        for (int j = 0; j < 64; j++) acc += Cmat[o * 64 + j] * W_mlp[j * 320 + m];
        g_CW[idx] = acc;
    }
    if (tid < 3) {
        float acc = 0.f;
        for (int j = 0; j < 64; j++) acc += Cmat[tid * 64 + j] * b_mlp[j];
        g_Cb[tid] = acc;
    }
    if (tid == 5) g_tcut = TT;   // default: correction active to the end

    for (int idx = tid; idx < 4096; idx += 512) {
        int i = idx >> 6, k = idx & 63;
        float v = W_hh[idx];
        s.A[i * PD + k]   = v;
        s.At[k * PD + i]  = v;
        s.cov[i * PD + k] = (i == k) ? 1.f : 0.f;
    }
    for (int idx = tid; idx < 192; idx += 512) { s.Cs[idx] = Cmat[idx]; s.Up[idx] = 0.f; }
    if (tid < 2) s.ctl[tid] = 0;
    if (tid == 0) s.done = 0;
    __syncthreads();

    const int ty = tid >> 4;       // 0..31 -> rows 2ty, 2ty+1
    const int tx = tid & 15;       // 0..15 -> cols 4tx..4tx+3
    const int i0 = 2 * ty;
    const int j0 = 4 * tx;

    for (int t = NHIST; t < TT; t++) {
        // ---- E = A @ cov  (2x4 tile per thread, f32x2) ----
        {
            unsigned long long e00 = 0, e01 = 0, e10 = 0, e11 = 0;
            #pragma unroll 4
            for (int k = 0; k < 64; k++) {
                unsigned long long b01 =
                    *(const unsigned long long*)&s.cov[k * PD + j0];
                unsigned long long b23 =
                    *(const unsigned long long*)&s.cov[k * PD + j0 + 2];
                float a0 = s.A[i0 * PD + k];
                float a1 = s.A[(i0 + 1) * PD + k];
                unsigned long long p0 = pack2(a0, a0), p1 = pack2(a1, a1);
                fma2(e00, p0, b01); fma2(e01, p0, b23);
                fma2(e10, p1, b01); fma2(e11, p1, b23);
            }
            *(float2*)&s.E[i0 * PD + j0]           = unpack2(e00);
            *(float2*)&s.E[i0 * PD + j0 + 2]       = unpack2(e01);
            *(float2*)&s.E[(i0 + 1) * PD + j0]     = unpack2(e10);
            *(float2*)&s.E[(i0 + 1) * PD + j0 + 2] = unpack2(e11);
        }
        __syncthreads();

        // ---- P = E @ A^T  (B operand = At rows, contiguous) ----
        {
            unsigned long long e00 = 0, e01 = 0, e10 = 0, e11 = 0;
            #pragma unroll 4
            for (int k = 0; k < 64; k++) {
                unsigned long long b01 =
                    *(const unsigned long long*)&s.At[k * PD + j0];
                unsigned long long b23 =
                    *(const unsigned long long*)&s.At[k * PD + j0 + 2];
                float a0 = s.E[i0 * PD + k];
                float a1 = s.E[(i0 + 1) * PD + k];
                unsigned long long p0 = pack2(a0, a0), p1 = pack2(a1, a1);
                fma2(e00, p0, b01); fma2(e01, p0, b23);
                fma2(e10, p1, b01); fma2(e11, p1, b23);
            }
            *(float2*)&s.P[i0 * PD + j0]           = unpack2(e00);
            *(float2*)&s.P[i0 * PD + j0 + 2]       = unpack2(e01);
            *(float2*)&s.P[(i0 + 1) * PD + j0]     = unpack2(e10);
            *(float2*)&s.P[(i0 + 1) * PD + j0 + 2] = unpack2(e11);
        }
        __syncthreads();

        // ---- Y = P @ C^T (64x3) ----
        if (tid < 192) {
            int o = tid >> 6, i = tid & 63;
            float acc = 0.f;
            for (int k = 0; k < 64; k++) acc += s.P[i * PD + k] * s.Cs[o * 64 + k];
            s.Y[i * 3 + o] = acc;
        }
        __syncthreads();

        // ---- S = C @ Y + I ----
        if (tid < 9) {
            int o1 = tid / 3, o2 = tid - o1 * 3;
            float acc = (o1 == o2) ? 1.f : 0.f;
            for (int k = 0; k < 64; k++) acc += s.Cs[o1 * 64 + k] * s.Y[k * 3 + o2];
            s.S[tid] = acc;
        }
        __syncthreads();

        // ---- Si = inv(S) ----
        if (tid == 0) {
            float a = s.S[0], b = s.S[1], c = s.S[2];
            float d = s.S[3], e = s.S[4], f = s.S[5];
            float g = s.S[6], h = s.S[7], i2 = s.S[8];
            float A0 =  (e * i2 - f * h);
            float A1 = -(d * i2 - f * g);
            float A2 =  (d * h  - e * g);
            float B0 = -(b * i2 - c * h);
            float B1 =  (a * i2 - c * g);
            float B2 = -(a * h  - b * g);
            float C0 =  (b * f - c * e);
            float C1 = -(a * f - c * d);
            float C2 =  (a * e - b * d);
            float det = a * A0 + b * A1 + c * A2;
            float id = 1.f / det;
            s.Si[0] = A0 * id; s.Si[1] = B0 * id; s.Si[2] = C0 * id;
            s.Si[3] = A1 * id; s.Si[4] = B1 * id; s.Si[5] = C1 * id;
            s.Si[6] = A2 * id; s.Si[7] = B2 * id; s.Si[8] = C2 * id;
        }
        __syncthreads();

        // ---- U = Y @ Si (K), store, track magnitude + delta ----
        if (tid < 192) {
            int o = tid >> 6, i = tid & 63;
            float u = s.Y[i * 3 + 0] * s.Si[0 + o]
                    + s.Y[i * 3 + 1] * s.Si[3 + o]
                    + s.Y[i * 3 + 2] * s.Si[6 + o];
            s.U[tid] = u;
            g_U[(size_t)t * 192 + tid] = u;
            float dd = fabsf(u - s.Up[tid]);
            s.Up[tid] = u;
            atomicMax(&s.ctl[0], __float_as_int(dd));
            atomicMax(&s.ctl[1], __float_as_int(fabsf(u)));
        }
        __syncthreads();

        // ---- CP = C @ P, exit decision ----
        if (tid < 192) {
            int o = tid >> 6, j = tid & 63;
            float acc = 0.f;
            for (int k = 0; k < 64; k++) acc += s.Cs[o * 64 + k] * s.P[k * PD + j];
            s.CP[tid] = acc;
        }
        if (tid == 0) {
            float md = __int_as_float(s.ctl[0]);
            float ma = __int_as_float(s.ctl[1]);
            if (ma <= 1e-6f)            s.done = 2;  // K negligible: tail = h_obs
            else if (md <= 1e-6f * ma)  s.done = 1;  // K stationary (nonzero)
            s.ctl[0] = 0; s.ctl[1] = 0;
        }
        __syncthreads();

        // ---- cov = P - U^T CP ----
        for (int e = tid; e < 4096; e += 512) {
            int i = e >> 6, j = e & 63;
            s.cov[i * PD + j] = s.P[i * PD + j]
                - (s.U[i]       * s.CP[j]
                 + s.U[64 + i]  * s.CP[64 + j]
                 + s.U[128 + i] * s.CP[128 + j]);
        }
        __syncthreads();

        if (s.done == 2) {            // K vanished: seq skips t >= t+1 entirely
            if (tid == 0) g_tcut = t + 1;
            break;
        }
        if (s.done == 1) {            // stationary nonzero K: fill the tail
            for (int tt = t + 1; tt < TT; tt++)
                for (int idx = tid; idx < 192; idx += 512)
                    g_U[(size_t)tt * 192 + idx] = s.U[idx];
            break;                    // g_tcut stays TT
        }
    }
}

// ======================================================================
// Consumer: block = 64 threads = 1 batch row; lane owns output dim
// j = tid. Weights register-stationary; per-step smem traffic is
// broadcast-only (h + x). One __syncthreads per step. Correction
// window known up-front via g_tcut (no per-step flag loads).
// ======================================================================
__global__ void __launch_bounds__(64, 1)
seq_kernel(const float* __restrict__ x,
           const float* __restrict__ W_ih, const float* __restrict__ b_ih,
           const float* __restrict__ W_hh, const float* __restrict__ b_hh,
           const float* __restrict__ C,
           float* __restrict__ out, float* __restrict__ hlast) {
    __shared__ __align__(16) float sh[2][64];   // parity-buffered hidden
    __shared__ __align__(16) float sx[2][32];   // parity-buffered x
    __shared__ float sred[2][4];                // correction warp partials

    const int tid  = threadIdx.x;
    const int w    = tid >> 5;
    const int lane = tid & 31;
    const int j    = tid;          // output dim owned by this lane
    const int row  = blockIdx.x;

    // ---- weights into registers (f32x2-packed) ----
    unsigned long long whh[32], wih[16];
    #pragma unroll
    for (int p = 0; p < 32; p++)
        whh[p] = *(const unsigned long long*)&W_hh[j * HH + 2 * p];
    #pragma unroll
    for (int p = 0; p < 16; p++)
        wih[p] = *(const unsigned long long*)&W_ih[j * IDM + 2 * p];

    const float Cj0 = C[j], Cj1 = C[64 + j], Cj2 = C[128 + j];
    const float bj  = b_ih[j] + b_hh[j];
    const float cb0 = g_Cb[0], cb1 = g_Cb[1], cb2 = g_Cb[2];
    const int   tcut = g_tcut;     // correction active iff NHIST <= t < tcut

    // ---- init state ----
    sh[0][j] = 0.f;
    float hcur = 0.f;
    float hist[NHIST] = {0.f, 0.f, 0.f, 0.f, 0.f};
    float xn1 = 0.f, xn2 = 0.f;
    if (w == 0) {
        sx[0][lane] = x[(size_t)row * IDM + lane];
        xn1 = x[((size_t)1 * BB + row) * IDM + lane];
        xn2 = x[((size_t)2 * BB + row) * IDM + lane];
    }
    float k0 = 0.f, k1 = 0.f, k2 = 0.f;
    int par = 0;
    __syncthreads();

    for (int t = 0; t < TT; t++) {
        // ---- prefetch x[t+3] and K[t+1] ----
        float xn3 = 0.f;
        if (w == 0 && t + 3 < TT)
            xn3 = x[((size_t)(t + 3) * BB + row) * IDM + lane];
        float kn0 = 0.f, kn1 = 0.f, kn2 = 0.f;
        if (t + 1 >= NHIST && t + 1 < tcut) {
            const float* Ut = &g_U[(size_t)(t + 1) * 192];
            kn0 = Ut[j]; kn1 = Ut[64 + j]; kn2 = Ut[128 + j];
        }

        // ---- GEMV: broadcast reads, register weights, FFMA2 ----
        unsigned long long a0 = 0, a1 = 0, a2 = 0, a3 = 0;
        const ulonglong2* hp = (const ulonglong2*)sh[par];
        #pragma unroll
        for (int q = 0; q < 16; q++) {
            ulonglong2 hv = hp[q];               // h[4q..4q+3]
            if (q & 1) { fma2(a2, hv.x, whh[2 * q]); fma2(a3, hv.y, whh[2 * q + 1]); }
            else       { fma2(a0, hv.x, whh[2 * q]); fma2(a1, hv.y, whh[2 * q + 1]); }
        }
        const ulonglong2* xp = (const ulonglong2*)sx[par];
        #pragma unroll
        for (int q = 0; q < 8; q++) {
            ulonglong2 xv = xp[q];               // x[4q..4q+3]
            if (q & 1) { fma2(a2, xv.x, wih[2 * q]); fma2(a3, xv.y, wih[2 * q + 1]); }
            else       { fma2(a0, xv.x, wih[2 * q]); fma2(a1, xv.y, wih[2 * q + 1]); }
        }
        float2 A0 = unpack2(a0), A1 = unpack2(a1), A2 = unpack2(a2), A3 = unpack2(a3);
        float pre = bj + (((A0.x + A0.y) + (A1.x + A1.y))
                        + ((A2.x + A2.y) + (A3.x + A3.y)));
        float ho = hcur * 0.8f + fmaxf(pre, 0.f) * 0.2f;

        // ---- Kalman correction (active only for NHIST <= t < tcut) ----
        if (t >= NHIST && t < tcut) {
            float p0 = -Cj0 * ho, p1 = -Cj1 * ho, p2 = -Cj2 * ho;
            #pragma unroll
            for (int sd = 0; sd < NHIST; sd++) {
                float hv = hist[sd];
                p0 += g_CW[0 * 320 + sd * 64 + j] * hv;
                p1 += g_CW[1 * 320 + sd * 64 + j] * hv;
                p2 += g_CW[2 * 320 + sd * 64 + j] * hv;
            }
            #pragma unroll
            for (int off = 16; off; off >>= 1) {
                p0 += __shfl_xor_sync(FULLM, p0, off);
                p1 += __shfl_xor_sync(FULLM, p1, off);
                p2 += __shfl_xor_sync(FULLM, p2, off);
            }
            if (lane == 0) {
                sred[w][0] = p0; sred[w][1] = p1; sred[w][2] = p2;
            }
            __syncthreads();
            p0 = sred[0][0] + sred[1][0] + cb0;
            p1 = sred[0][1] + sred[1][1] + cb1;
            p2 = sred[0][2] + sred[1][2] + cb2;
            ho += k0 * p0 + k1 * p1 + k2 * p2;
        }

        // ---- history shift (dead once the correction window closes) ----
        if (t + 1 < tcut) {
            #pragma unroll
            for (int sd = 0; sd < NHIST - 1; sd++) hist[sd] = hist[sd + 1];
            hist[NHIST - 1] = ho;
        }

        // ---- publish state, write output, advance pipeline ----
        sh[par ^ 1][j] = ho;
        if (w == 0) sx[par ^ 1][lane] = xn1;
        out[((size_t)t * BB + row) * HH + j] = ho;
        __syncthreads();

        hcur = ho;
        xn1 = xn2; xn2 = xn3;
        k0 = kn0; k1 = kn1; k2 = kn2;
        par ^= 1;
    }

    if (hlast) hlast[(size_t)row * HH + j] = hcur;
}

// ======================================================================
extern "C" void kernel_launch(void* const* d_in, const int* in_sizes, int n_in,
                              void* d_out, int out_size) {
    const float* x     = (const float*)d_in[0];
    const float* W_ih  = (const float*)d_in[1];
    const float* b_ih  = (const float*)d_in[2];
    const float* W_hh  = (const float*)d_in[3];
    const float* b_hh  = (const float*)d_in[4];
    const float* C     = (const float*)d_in[5];
    const float* W_mlp = (const float*)d_in[6];
    const float* b_mlp = (const float*)d_in[7];
    float* out = (float*)d_out;

    const long long main_elems = (long long)TT * BB * HH;
    float* hlast = ((long long)out_size >= main_elems + (long long)BB * HH)
                       ? out + main_elems : nullptr;

    cudaFuncSetAttribute(cov_kernel, cudaFuncAttributeMaxDynamicSharedMemorySize,
                         (int)sizeof(PSmem));

    cov_kernel<<<1, 512, sizeof(PSmem)>>>(W_hh, C, W_mlp, b_mlp);
    seq_kernel<<<BB, 64>>>(x, W_ih, b_ih, W_hh, b_hh, C, out, hlast);
}